// round 5
// baseline (speedup 1.0000x reference)
#include <cuda_runtime.h>
#include <math.h>

#define N_USERS 100000
#define N_ITEMS 200000
#define N_NODES 300000
#define EMB_DIM 64
#define VEC     16          // float4s per row
#define N_EDGES 4000000
#define BATCH   8192
#define EMB_REG 2.5e-05f
#define SCAN_BLK 256
#define NBLK ((N_NODES + SCAN_BLK - 1) / SCAN_BLK)   // 1172

// ---------------- scratch (device globals) ----------------
static __device__ int    g_cnt   [N_NODES];
static __device__ int    g_rowptr[N_NODES + 1];
static __device__ int    g_cursor[N_NODES];
static __device__ int    g_blksum[NBLK];
static __device__ float  g_dinv  [N_NODES];
static __device__ int2   g_edge  [N_EDGES];      // (t, w-as-int) sorted by h
static __device__ float4 g_E  [(size_t)N_NODES * VEC];
static __device__ float4 g_N  [(size_t)N_NODES * VEC];
static __device__ float4 g_ACC[(size_t)N_NODES * VEC];

// ---------------- kernels ----------------

__global__ void k_zero(float* out) {
    int i = blockIdx.x * blockDim.x + threadIdx.x;
    if (i < N_NODES) g_cnt[i] = 0;
    if (i < 2)       out[i]   = 0.0f;
}

__global__ void k_deg(const int* __restrict__ h) {
    int e = blockIdx.x * blockDim.x + threadIdx.x;
    if (e < N_EDGES) atomicAdd(&g_cnt[__ldg(h + e)], 1);
}

// block-local exclusive scan; block totals to g_blksum
__global__ void k_scan1() {
    __shared__ int sh[SCAN_BLK];
    int i = blockIdx.x * SCAN_BLK + threadIdx.x;
    int v = (i < N_NODES) ? g_cnt[i] : 0;
    sh[threadIdx.x] = v;
    __syncthreads();
    for (int o = 1; o < SCAN_BLK; o <<= 1) {
        int t = (threadIdx.x >= o) ? sh[threadIdx.x - o] : 0;
        __syncthreads();
        sh[threadIdx.x] += t;
        __syncthreads();
    }
    if (i < N_NODES) g_rowptr[i] = sh[threadIdx.x] - v;          // exclusive
    if (threadIdx.x == SCAN_BLK - 1) g_blksum[blockIdx.x] = sh[SCAN_BLK - 1];
}

// single-block exclusive scan of the block sums
__global__ void k_scan2() {
    __shared__ int sh[1024];
    __shared__ int carry;
    int tid = threadIdx.x;
    if (tid == 0) carry = 0;
    __syncthreads();
    for (int base = 0; base < NBLK; base += 1024) {
        int i = base + tid;
        int v = (i < NBLK) ? g_blksum[i] : 0;
        sh[tid] = v;
        __syncthreads();
        for (int o = 1; o < 1024; o <<= 1) {
            int t = (tid >= o) ? sh[tid - o] : 0;
            __syncthreads();
            sh[tid] += t;
            __syncthreads();
        }
        if (i < NBLK) g_blksum[i] = sh[tid] - v + carry;
        __syncthreads();
        if (tid == 0) carry += sh[1023];
        __syncthreads();
    }
}

// finalize rowptr, init cursor, compute dinv
__global__ void k_scan3() {
    int i = blockIdx.x * blockDim.x + threadIdx.x;
    if (i < N_NODES) {
        int rp = g_rowptr[i] + g_blksum[i >> 8];
        g_rowptr[i] = rp;
        g_cursor[i] = rp;
        int c = g_cnt[i];
        g_dinv[i] = (c > 0) ? rsqrtf((float)c) : 0.0f;
    }
    if (i == 0) g_rowptr[N_NODES] = N_EDGES;
}

// counting-sort scatter: bucket edges by h; packed (t, w) payload
__global__ void k_scatter(const int* __restrict__ h, const int* __restrict__ t) {
    int e = blockIdx.x * blockDim.x + threadIdx.x;
    if (e >= N_EDGES) return;
    int hh = __ldg(h + e);
    int tt = __ldg(t + e);
    int slot = atomicAdd(&g_cursor[hh], 1);
    float w = g_dinv[hh] * g_dinv[tt];
    g_edge[slot] = make_int2(tt, __float_as_int(w));
}

// E = concat(user_emb, item_emb); ACC = E
__global__ void k_init(const float* __restrict__ ue, const float* __restrict__ ie) {
    int i = blockIdx.x * blockDim.x + threadIdx.x;
    const int TOT = N_NODES * VEC;
    if (i >= TOT) return;
    const int UQ = N_USERS * VEC;
    float4 v = (i < UQ) ? __ldg(reinterpret_cast<const float4*>(ue) + i)
                        : __ldg(reinterpret_cast<const float4*>(ie) + (i - UQ));
    g_E[i]   = v;
    g_ACC[i] = v;
}

// warp-per-row CSR SpMM, unroll-4 batched gathers, fused residual + ACC (+ N write)
__global__ void k_csr(int layer) {
    int wg   = (blockIdx.x * blockDim.x + threadIdx.x) >> 5;
    int lane = threadIdx.x & 31;
    if (wg >= N_NODES) return;
    const float2* __restrict__ src = reinterpret_cast<const float2*>(layer == 0 ? g_E : g_N);

    int beg = g_rowptr[wg];
    int end = g_rowptr[wg + 1];
    float accx = 0.0f, accy = 0.0f;

    int e = beg;
    for (; e + 4 <= end; e += 4) {
        // batch the edge descriptors (uniform broadcast loads)
        int2 d0 = __ldg(g_edge + e + 0);
        int2 d1 = __ldg(g_edge + e + 1);
        int2 d2 = __ldg(g_edge + e + 2);
        int2 d3 = __ldg(g_edge + e + 3);
        // issue 4 independent row gathers before consuming any
        float2 v0 = __ldg(&src[(size_t)d0.x * 32 + lane]);
        float2 v1 = __ldg(&src[(size_t)d1.x * 32 + lane]);
        float2 v2 = __ldg(&src[(size_t)d2.x * 32 + lane]);
        float2 v3 = __ldg(&src[(size_t)d3.x * 32 + lane]);
        float w0 = __int_as_float(d0.y), w1 = __int_as_float(d1.y);
        float w2 = __int_as_float(d2.y), w3 = __int_as_float(d3.y);
        accx += w0 * v0.x + w1 * v1.x + w2 * v2.x + w3 * v3.x;
        accy += w0 * v0.y + w1 * v1.y + w2 * v2.y + w3 * v3.y;
    }
    for (; e < end; ++e) {
        int2 d0 = __ldg(g_edge + e);
        float2 v0 = __ldg(&src[(size_t)d0.x * 32 + lane]);
        float w0 = __int_as_float(d0.y);
        accx += w0 * v0.x;
        accy += w0 * v0.y;
    }

    size_t idx = (size_t)wg * 32 + lane;
    float2 old = src[idx];
    float2 nw  = make_float2(accx + old.x, accy + old.y);

    float2* accp = reinterpret_cast<float2*>(g_ACC);
    float2 a = accp[idx];
    a.x += nw.x; a.y += nw.y;
    accp[idx] = a;

    if (layer == 0) reinterpret_cast<float2*>(g_N)[idx] = nw;
}

// one warp per sample
__global__ void k_loss(const float* __restrict__ ue, const float* __restrict__ ie,
                       const int* __restrict__ users, const int* __restrict__ pos,
                       const int* __restrict__ neg, float* __restrict__ out) {
    int warp = (blockIdx.x * blockDim.x + threadIdx.x) >> 5;
    int lane = threadIdx.x & 31;
    if (warp >= BATCH) return;
    int u = users[warp], p = pos[warp], n = neg[warp];

    const float2* accp = reinterpret_cast<const float2*>(g_ACC);
    float2 uv = accp[(size_t)u * 32 + lane];
    float2 pv = accp[(size_t)(N_USERS + p) * 32 + lane];
    float2 nv = accp[(size_t)(N_USERS + n) * 32 + lane];
    float s = uv.x * (nv.x - pv.x) + uv.y * (nv.y - pv.y);   // neg - pos partial

    const float2* up = reinterpret_cast<const float2*>(ue + (size_t)u * EMB_DIM);
    const float2* pp = reinterpret_cast<const float2*>(ie + (size_t)p * EMB_DIM);
    const float2* np = reinterpret_cast<const float2*>(ie + (size_t)n * EMB_DIM);
    float2 a = up[lane], b = pp[lane], c = np[lane];
    float r = a.x*a.x + a.y*a.y + b.x*b.x + b.y*b.y + c.x*c.x + c.y*c.y;

    #pragma unroll
    for (int o = 16; o; o >>= 1) {
        s += __shfl_xor_sync(0xFFFFFFFFu, s, o);
        r += __shfl_xor_sync(0xFFFFFFFFu, r, o);
    }
    if (lane == 0) {
        float x  = s;
        float sp = (x > 0.0f) ? x + log1pf(expf(-x)) : log1pf(expf(x));
        atomicAdd(&out[0], sp * (1.0f / BATCH));
        atomicAdd(&out[1], r * EMB_REG);
    }
}

// ---------------- launch ----------------
extern "C" void kernel_launch(void* const* d_in, const int* in_sizes, int n_in,
                              void* d_out, int out_size) {
    const float* ue    = (const float*)d_in[0];
    const float* ie    = (const float*)d_in[1];
    const int*   all_h = (const int*)  d_in[2];
    const int*   all_t = (const int*)  d_in[3];
    const int*   users = (const int*)  d_in[4];
    const int*   pos   = (const int*)  d_in[5];
    const int*   neg   = (const int*)  d_in[6];
    float*       out   = (float*)d_out;

    const int T = 256;
    const int gNode = (N_NODES + T - 1) / T;
    const int gEdge = (N_EDGES + T - 1) / T;
    const int gVec  = (N_NODES * VEC + T - 1) / T;
    const int gCsr  = ((N_NODES * 32) + T - 1) / T;   // warp per row

    k_zero   <<<gNode, T>>>(out);
    k_deg    <<<gEdge, T>>>(all_h);
    k_scan1  <<<NBLK, SCAN_BLK>>>();
    k_scan2  <<<1, 1024>>>();
    k_scan3  <<<gNode, T>>>();
    k_scatter<<<gEdge, T>>>(all_h, all_t);
    k_init   <<<gVec,  T>>>(ue, ie);

    k_csr<<<gCsr, T>>>(0);
    k_csr<<<gCsr, T>>>(1);

    k_loss<<<(BATCH * 32 + T - 1) / T, T>>>(ue, ie, users, pos, neg, out);
}

// round 9
// speedup vs baseline: 1.0625x; 1.0625x over previous
#include <cuda_runtime.h>
#include <math.h>

#define N_USERS 100000
#define N_ITEMS 200000
#define N_NODES 300000
#define EMB_DIM 64
#define VEC     16          // float4s per row
#define N_EDGES 4000000
#define BATCH   8192
#define EMB_REG 2.5e-05f
#define SCAN_BLK 256
#define NBLK ((N_NODES + SCAN_BLK - 1) / SCAN_BLK)   // 1172

// ---------------- scratch (device globals) ----------------
static __device__ int    g_cnt   [N_NODES];
static __device__ int    g_rowptr[N_NODES + 1];
static __device__ int    g_cursor[N_NODES];
static __device__ int    g_blksum[NBLK];
static __device__ float  g_dinv  [N_NODES];
static __device__ int    g_ts    [N_EDGES];      // CSR col indices, sorted by h
static __device__ float  g_gs    [N_EDGES];      // CSR edge weights
static __device__ float4 g_E  [(size_t)N_NODES * VEC];
static __device__ float4 g_N  [(size_t)N_NODES * VEC];
static __device__ float4 g_ACC[(size_t)N_NODES * VEC];

// ---------------- kernels ----------------

__global__ void k_zero(float* out) {
    int i = blockIdx.x * blockDim.x + threadIdx.x;
    if (i < N_NODES) g_cnt[i] = 0;
    if (i < 2)       out[i]   = 0.0f;
}

__global__ void k_deg(const int* __restrict__ h) {
    int e = blockIdx.x * blockDim.x + threadIdx.x;
    if (e < N_EDGES) atomicAdd(&g_cnt[__ldg(h + e)], 1);
}

// block-local exclusive scan; block totals to g_blksum
__global__ void k_scan1() {
    __shared__ int sh[SCAN_BLK];
    int i = blockIdx.x * SCAN_BLK + threadIdx.x;
    int v = (i < N_NODES) ? g_cnt[i] : 0;
    sh[threadIdx.x] = v;
    __syncthreads();
    for (int o = 1; o < SCAN_BLK; o <<= 1) {
        int t = (threadIdx.x >= o) ? sh[threadIdx.x - o] : 0;
        __syncthreads();
        sh[threadIdx.x] += t;
        __syncthreads();
    }
    if (i < N_NODES) g_rowptr[i] = sh[threadIdx.x] - v;          // exclusive
    if (threadIdx.x == SCAN_BLK - 1) g_blksum[blockIdx.x] = sh[SCAN_BLK - 1];
}

// single-block exclusive scan of the block sums
__global__ void k_scan2() {
    __shared__ int sh[1024];
    __shared__ int carry;
    int tid = threadIdx.x;
    if (tid == 0) carry = 0;
    __syncthreads();
    for (int base = 0; base < NBLK; base += 1024) {
        int i = base + tid;
        int v = (i < NBLK) ? g_blksum[i] : 0;
        sh[tid] = v;
        __syncthreads();
        for (int o = 1; o < 1024; o <<= 1) {
            int t = (tid >= o) ? sh[tid - o] : 0;
            __syncthreads();
            sh[tid] += t;
            __syncthreads();
        }
        if (i < NBLK) g_blksum[i] = sh[tid] - v + carry;
        __syncthreads();
        if (tid == 0) carry += sh[1023];
        __syncthreads();
    }
}

// finalize rowptr, init cursor, compute dinv
__global__ void k_scan3() {
    int i = blockIdx.x * blockDim.x + threadIdx.x;
    if (i < N_NODES) {
        int rp = g_rowptr[i] + g_blksum[i >> 8];
        g_rowptr[i] = rp;
        g_cursor[i] = rp;
        int c = g_cnt[i];
        g_dinv[i] = (c > 0) ? rsqrtf((float)c) : 0.0f;
    }
    if (i == 0) g_rowptr[N_NODES] = N_EDGES;
}

// counting-sort scatter: bucket edges by h
__global__ void k_scatter(const int* __restrict__ h, const int* __restrict__ t) {
    int e = blockIdx.x * blockDim.x + threadIdx.x;
    if (e >= N_EDGES) return;
    int hh = __ldg(h + e);
    int tt = __ldg(t + e);
    int slot = atomicAdd(&g_cursor[hh], 1);
    g_ts[slot] = tt;
    g_gs[slot] = g_dinv[hh] * g_dinv[tt];
}

// E = concat(user_emb, item_emb); ACC = E
__global__ void k_init(const float* __restrict__ ue, const float* __restrict__ ie) {
    int i = blockIdx.x * blockDim.x + threadIdx.x;
    const int TOT = N_NODES * VEC;
    if (i >= TOT) return;
    const int UQ = N_USERS * VEC;
    float4 v = (i < UQ) ? __ldg(reinterpret_cast<const float4*>(ue) + i)
                        : __ldg(reinterpret_cast<const float4*>(ie) + (i - UQ));
    g_E[i]   = v;
    g_ACC[i] = v;
}

// warp-per-row CSR SpMM: coalesced descriptor prefetch + shfl broadcast,
// unroll-2 gather batching (MLP=2), fused residual + ACC (+ N write)
__global__ void __launch_bounds__(256) k_csr(int layer) {
    int wg   = (blockIdx.x * blockDim.x + threadIdx.x) >> 5;
    int lane = threadIdx.x & 31;
    if (wg >= N_NODES) return;
    const float2* __restrict__ src = reinterpret_cast<const float2*>(layer == 0 ? g_E : g_N);

    int beg = g_rowptr[wg];
    int end = g_rowptr[wg + 1];
    float accx = 0.0f, accy = 0.0f;

    for (int base = beg; base < end; base += 32) {
        int n = end - base;
        if (n > 32) n = 32;
        // one coalesced descriptor load per lane for up to 32 edges
        int   myt = 0;
        float myw = 0.0f;
        if (lane < n) {
            myt = __ldg(g_ts + base + lane);
            myw = __ldg(g_gs + base + lane);
        }
        int j = 0;
        for (; j + 2 <= n; j += 2) {
            int   t0 = __shfl_sync(0xFFFFFFFFu, myt, j);
            int   t1 = __shfl_sync(0xFFFFFFFFu, myt, j + 1);
            float w0 = __shfl_sync(0xFFFFFFFFu, myw, j);
            float w1 = __shfl_sync(0xFFFFFFFFu, myw, j + 1);
            float2 v0 = __ldg(&src[(size_t)t0 * 32 + lane]);
            float2 v1 = __ldg(&src[(size_t)t1 * 32 + lane]);
            accx += w0 * v0.x + w1 * v1.x;
            accy += w0 * v0.y + w1 * v1.y;
        }
        if (j < n) {
            int   t0 = __shfl_sync(0xFFFFFFFFu, myt, j);
            float w0 = __shfl_sync(0xFFFFFFFFu, myw, j);
            float2 v0 = __ldg(&src[(size_t)t0 * 32 + lane]);
            accx += w0 * v0.x;
            accy += w0 * v0.y;
        }
    }

    size_t idx = (size_t)wg * 32 + lane;
    float2 old = src[idx];
    float2 nw  = make_float2(accx + old.x, accy + old.y);

    float2* accp = reinterpret_cast<float2*>(g_ACC);
    float2 a = accp[idx];
    a.x += nw.x; a.y += nw.y;
    accp[idx] = a;

    if (layer == 0) reinterpret_cast<float2*>(g_N)[idx] = nw;
}

// one warp per sample
__global__ void k_loss(const float* __restrict__ ue, const float* __restrict__ ie,
                       const int* __restrict__ users, const int* __restrict__ pos,
                       const int* __restrict__ neg, float* __restrict__ out) {
    int warp = (blockIdx.x * blockDim.x + threadIdx.x) >> 5;
    int lane = threadIdx.x & 31;
    if (warp >= BATCH) return;
    int u = users[warp], p = pos[warp], n = neg[warp];

    const float2* accp = reinterpret_cast<const float2*>(g_ACC);
    float2 uv = accp[(size_t)u * 32 + lane];
    float2 pv = accp[(size_t)(N_USERS + p) * 32 + lane];
    float2 nv = accp[(size_t)(N_USERS + n) * 32 + lane];
    float s = uv.x * (nv.x - pv.x) + uv.y * (nv.y - pv.y);   // neg - pos partial

    const float2* up = reinterpret_cast<const float2*>(ue + (size_t)u * EMB_DIM);
    const float2* pp = reinterpret_cast<const float2*>(ie + (size_t)p * EMB_DIM);
    const float2* np = reinterpret_cast<const float2*>(ie + (size_t)n * EMB_DIM);
    float2 a = up[lane], b = pp[lane], c = np[lane];
    float r = a.x*a.x + a.y*a.y + b.x*b.x + b.y*b.y + c.x*c.x + c.y*c.y;

    #pragma unroll
    for (int o = 16; o; o >>= 1) {
        s += __shfl_xor_sync(0xFFFFFFFFu, s, o);
        r += __shfl_xor_sync(0xFFFFFFFFu, r, o);
    }
    if (lane == 0) {
        float x  = s;
        float sp = (x > 0.0f) ? x + log1pf(expf(-x)) : log1pf(expf(x));
        atomicAdd(&out[0], sp * (1.0f / BATCH));
        atomicAdd(&out[1], r * EMB_REG);
    }
}

// ---------------- launch ----------------
extern "C" void kernel_launch(void* const* d_in, const int* in_sizes, int n_in,
                              void* d_out, int out_size) {
    const float* ue    = (const float*)d_in[0];
    const float* ie    = (const float*)d_in[1];
    const int*   all_h = (const int*)  d_in[2];
    const int*   all_t = (const int*)  d_in[3];
    const int*   users = (const int*)  d_in[4];
    const int*   pos   = (const int*)  d_in[5];
    const int*   neg   = (const int*)  d_in[6];
    float*       out   = (float*)d_out;

    const int T = 256;
    const int gNode = (N_NODES + T - 1) / T;
    const int gEdge = (N_EDGES + T - 1) / T;
    const int gVec  = (N_NODES * VEC + T - 1) / T;
    const int gCsr  = ((N_NODES * 32) + T - 1) / T;   // warp per row

    k_zero   <<<gNode, T>>>(out);
    k_deg    <<<gEdge, T>>>(all_h);
    k_scan1  <<<NBLK, SCAN_BLK>>>();
    k_scan2  <<<1, 1024>>>();
    k_scan3  <<<gNode, T>>>();
    k_scatter<<<gEdge, T>>>(all_h, all_t);
    k_init   <<<gVec,  T>>>(ue, ie);

    k_csr<<<gCsr, T>>>(0);
    k_csr<<<gCsr, T>>>(1);

    k_loss<<<(BATCH * 32 + T - 1) / T, T>>>(ue, ie, users, pos, neg, out);
}

// round 11
// speedup vs baseline: 1.2485x; 1.1751x over previous
#include <cuda_runtime.h>
#include <math.h>

#define N_USERS 100000
#define N_ITEMS 200000
#define N_NODES 300000
#define EMB_DIM 64
#define VEC     16          // float4s per row
#define N_EDGES 4000000
#define BATCH   8192
#define EMB_REG 2.5e-05f
#define SCAN_BLK 256
#define NBLK ((N_NODES + SCAN_BLK - 1) / SCAN_BLK)   // 1172

// ---------------- scratch (device globals) ----------------
static __device__ int    g_cnt   [N_NODES];
static __device__ int    g_rowptr[N_NODES + 1];
static __device__ int    g_cursor[N_NODES];
static __device__ int    g_blksum[NBLK];
static __device__ float  g_dinv  [N_NODES];
static __device__ int    g_ts    [N_EDGES];      // CSR col indices, sorted by h
static __device__ float  g_gs    [N_EDGES];      // CSR edge weights
static __device__ float4 g_E0 [(size_t)N_NODES * VEC];   // layer-0 (input) embeddings
static __device__ float4 g_E1 [(size_t)N_NODES * VEC];   // after layer 1
static __device__ float4 g_E2 [(size_t)N_NODES * VEC];   // after layer 2

// ---------------- kernels ----------------

__global__ void k_zero(float* out) {
    int i = blockIdx.x * blockDim.x + threadIdx.x;
    if (i < N_NODES) g_cnt[i] = 0;
    if (i < 2)       out[i]   = 0.0f;
}

__global__ void k_deg(const int* __restrict__ h) {
    int e = blockIdx.x * blockDim.x + threadIdx.x;
    if (e < N_EDGES) atomicAdd(&g_cnt[__ldg(h + e)], 1);
}

// block-local exclusive scan; block totals to g_blksum
__global__ void k_scan1() {
    __shared__ int sh[SCAN_BLK];
    int i = blockIdx.x * SCAN_BLK + threadIdx.x;
    int v = (i < N_NODES) ? g_cnt[i] : 0;
    sh[threadIdx.x] = v;
    __syncthreads();
    for (int o = 1; o < SCAN_BLK; o <<= 1) {
        int t = (threadIdx.x >= o) ? sh[threadIdx.x - o] : 0;
        __syncthreads();
        sh[threadIdx.x] += t;
        __syncthreads();
    }
    if (i < N_NODES) g_rowptr[i] = sh[threadIdx.x] - v;          // exclusive
    if (threadIdx.x == SCAN_BLK - 1) g_blksum[blockIdx.x] = sh[SCAN_BLK - 1];
}

// single-block exclusive scan of the block sums
__global__ void k_scan2() {
    __shared__ int sh[1024];
    __shared__ int carry;
    int tid = threadIdx.x;
    if (tid == 0) carry = 0;
    __syncthreads();
    for (int base = 0; base < NBLK; base += 1024) {
        int i = base + tid;
        int v = (i < NBLK) ? g_blksum[i] : 0;
        sh[tid] = v;
        __syncthreads();
        for (int o = 1; o < 1024; o <<= 1) {
            int t = (tid >= o) ? sh[tid - o] : 0;
            __syncthreads();
            sh[tid] += t;
            __syncthreads();
        }
        if (i < NBLK) g_blksum[i] = sh[tid] - v + carry;
        __syncthreads();
        if (tid == 0) carry += sh[1023];
        __syncthreads();
    }
}

// finalize rowptr, init cursor, compute dinv
__global__ void k_scan3() {
    int i = blockIdx.x * blockDim.x + threadIdx.x;
    if (i < N_NODES) {
        int rp = g_rowptr[i] + g_blksum[i >> 8];
        g_rowptr[i] = rp;
        g_cursor[i] = rp;
        int c = g_cnt[i];
        g_dinv[i] = (c > 0) ? rsqrtf((float)c) : 0.0f;
    }
    if (i == 0) g_rowptr[N_NODES] = N_EDGES;
}

// counting-sort scatter: bucket edges by h
__global__ void k_scatter(const int* __restrict__ h, const int* __restrict__ t) {
    int e = blockIdx.x * blockDim.x + threadIdx.x;
    if (e >= N_EDGES) return;
    int hh = __ldg(h + e);
    int tt = __ldg(t + e);
    int slot = atomicAdd(&g_cursor[hh], 1);
    g_ts[slot] = tt;
    g_gs[slot] = g_dinv[hh] * g_dinv[tt];
}

// E0 = concat(user_emb, item_emb)
__global__ void k_init(const float* __restrict__ ue, const float* __restrict__ ie) {
    int i = blockIdx.x * blockDim.x + threadIdx.x;
    const int TOT = N_NODES * VEC;
    if (i >= TOT) return;
    const int UQ = N_USERS * VEC;
    float4 v = (i < UQ) ? __ldg(reinterpret_cast<const float4*>(ue) + i)
                        : __ldg(reinterpret_cast<const float4*>(ie) + (i - UQ));
    g_E0[i] = v;
}

// warp-per-row CSR SpMM (R4-proven inner loop: unroll-2, direct descriptor LDGs)
// dst[row] = sum_e w_e * src[t_e] + src[row]
__global__ void __launch_bounds__(256) k_csr(int layer) {
    int wg   = (blockIdx.x * blockDim.x + threadIdx.x) >> 5;
    int lane = threadIdx.x & 31;
    if (wg >= N_NODES) return;
    const float2* __restrict__ src = reinterpret_cast<const float2*>(layer == 0 ? g_E0 : g_E1);
    float2*       __restrict__ dst = reinterpret_cast<float2*>(layer == 0 ? g_E1 : g_E2);

    int beg = g_rowptr[wg];
    int end = g_rowptr[wg + 1];
    float accx = 0.0f, accy = 0.0f;

    int e = beg;
    for (; e + 2 <= end; e += 2) {
        int   t0 = __ldg(g_ts + e),     t1 = __ldg(g_ts + e + 1);
        float w0 = __ldg(g_gs + e),     w1 = __ldg(g_gs + e + 1);
        float2 v0 = __ldg(&src[(size_t)t0 * 32 + lane]);
        float2 v1 = __ldg(&src[(size_t)t1 * 32 + lane]);
        accx += w0 * v0.x + w1 * v1.x;
        accy += w0 * v0.y + w1 * v1.y;
    }
    if (e < end) {
        int   t0 = __ldg(g_ts + e);
        float w0 = __ldg(g_gs + e);
        float2 v0 = __ldg(&src[(size_t)t0 * 32 + lane]);
        accx += w0 * v0.x;
        accy += w0 * v0.y;
    }

    size_t idx = (size_t)wg * 32 + lane;
    float2 old = __ldg(&src[idx]);
    dst[idx] = make_float2(accx + old.x, accy + old.y);
}

// one warp per sample; acc row = E0 + E1 + E2 gathered on the fly
__global__ void k_loss(const float* __restrict__ ue, const float* __restrict__ ie,
                       const int* __restrict__ users, const int* __restrict__ pos,
                       const int* __restrict__ neg, float* __restrict__ out) {
    int warp = (blockIdx.x * blockDim.x + threadIdx.x) >> 5;
    int lane = threadIdx.x & 31;
    if (warp >= BATCH) return;
    int u = users[warp], p = pos[warp], n = neg[warp];

    const float2* e0 = reinterpret_cast<const float2*>(g_E0);
    const float2* e1 = reinterpret_cast<const float2*>(g_E1);
    const float2* e2 = reinterpret_cast<const float2*>(g_E2);

    size_t ui = (size_t)u * 32 + lane;
    size_t pi = (size_t)(N_USERS + p) * 32 + lane;
    size_t ni = (size_t)(N_USERS + n) * 32 + lane;

    float2 u0 = __ldg(e0 + ui), u1 = __ldg(e1 + ui), u2 = __ldg(e2 + ui);
    float2 p0 = __ldg(e0 + pi), p1 = __ldg(e1 + pi), p2 = __ldg(e2 + pi);
    float2 n0 = __ldg(e0 + ni), n1 = __ldg(e1 + ni), n2 = __ldg(e2 + ni);

    float2 uv = make_float2(u0.x + u1.x + u2.x, u0.y + u1.y + u2.y);
    float2 pv = make_float2(p0.x + p1.x + p2.x, p0.y + p1.y + p2.y);
    float2 nv = make_float2(n0.x + n1.x + n2.x, n0.y + n1.y + n2.y);
    float s = uv.x * (nv.x - pv.x) + uv.y * (nv.y - pv.y);   // neg - pos partial

    const float2* up = reinterpret_cast<const float2*>(ue + (size_t)u * EMB_DIM);
    const float2* pp = reinterpret_cast<const float2*>(ie + (size_t)p * EMB_DIM);
    const float2* np = reinterpret_cast<const float2*>(ie + (size_t)n * EMB_DIM);
    float2 a = __ldg(up + lane), b = __ldg(pp + lane), c = __ldg(np + lane);
    float r = a.x*a.x + a.y*a.y + b.x*b.x + b.y*b.y + c.x*c.x + c.y*c.y;

    #pragma unroll
    for (int o = 16; o; o >>= 1) {
        s += __shfl_xor_sync(0xFFFFFFFFu, s, o);
        r += __shfl_xor_sync(0xFFFFFFFFu, r, o);
    }
    if (lane == 0) {
        float x  = s;
        float sp = (x > 0.0f) ? x + log1pf(expf(-x)) : log1pf(expf(x));
        atomicAdd(&out[0], sp * (1.0f / BATCH));
        atomicAdd(&out[1], r * EMB_REG);
    }
}

// ---------------- launch ----------------
extern "C" void kernel_launch(void* const* d_in, const int* in_sizes, int n_in,
                              void* d_out, int out_size) {
    const float* ue    = (const float*)d_in[0];
    const float* ie    = (const float*)d_in[1];
    const int*   all_h = (const int*)  d_in[2];
    const int*   all_t = (const int*)  d_in[3];
    const int*   users = (const int*)  d_in[4];
    const int*   pos   = (const int*)  d_in[5];
    const int*   neg   = (const int*)  d_in[6];
    float*       out   = (float*)d_out;

    const int T = 256;
    const int gNode = (N_NODES + T - 1) / T;
    const int gEdge = (N_EDGES + T - 1) / T;
    const int gVec  = (N_NODES * VEC + T - 1) / T;
    const int gCsr  = ((N_NODES * 32) + T - 1) / T;   // warp per row

    k_zero   <<<gNode, T>>>(out);
    k_deg    <<<gEdge, T>>>(all_h);
    k_scan1  <<<NBLK, SCAN_BLK>>>();
    k_scan2  <<<1, 1024>>>();
    k_scan3  <<<gNode, T>>>();
    k_scatter<<<gEdge, T>>>(all_h, all_t);
    k_init   <<<gVec,  T>>>(ue, ie);

    k_csr<<<gCsr, T>>>(0);
    k_csr<<<gCsr, T>>>(1);

    k_loss<<<(BATCH * 32 + T - 1) / T, T>>>(ue, ie, users, pos, neg, out);
}

// round 12
// speedup vs baseline: 1.2568x; 1.0066x over previous
#include <cuda_runtime.h>
#include <math.h>

#define N_USERS 100000
#define N_ITEMS 200000
#define N_NODES 300000
#define EMB_DIM 64
#define VEC     16          // float4s per row
#define N_EDGES 4000000
#define BATCH   8192
#define EMB_REG 2.5e-05f
#define SCAN_BLK 256
#define NBLK ((N_NODES + SCAN_BLK - 1) / SCAN_BLK)   // 1172

// ---------------- scratch (device globals) ----------------
static __device__ int    g_cnt   [N_NODES];
static __device__ int    g_rowptr[N_NODES + 1];
static __device__ int    g_cursor[N_NODES];
static __device__ int    g_blksum[NBLK];
static __device__ float  g_dinv  [N_NODES];
static __device__ int    g_ts    [N_EDGES];      // CSR col indices, sorted by h
static __device__ float  g_gs    [N_EDGES];      // CSR edge weights
static __device__ float4 g_E0 [(size_t)N_NODES * VEC];   // layer-0 (input) embeddings
static __device__ float4 g_E1 [(size_t)N_NODES * VEC];   // after layer 1
static __device__ float4 g_E2 [(size_t)N_NODES * VEC];   // after layer 2

// ---------------- kernels ----------------

__global__ void k_zero(float* out) {
    int i = blockIdx.x * blockDim.x + threadIdx.x;
    if (i < N_NODES) g_cnt[i] = 0;
    if (i < 2)       out[i]   = 0.0f;
}

__global__ void k_deg(const int* __restrict__ h) {
    int e = blockIdx.x * blockDim.x + threadIdx.x;
    if (e < N_EDGES) atomicAdd(&g_cnt[__ldg(h + e)], 1);
}

// block-local exclusive scan; block totals to g_blksum
__global__ void k_scan1() {
    __shared__ int sh[SCAN_BLK];
    int i = blockIdx.x * SCAN_BLK + threadIdx.x;
    int v = (i < N_NODES) ? g_cnt[i] : 0;
    sh[threadIdx.x] = v;
    __syncthreads();
    for (int o = 1; o < SCAN_BLK; o <<= 1) {
        int t = (threadIdx.x >= o) ? sh[threadIdx.x - o] : 0;
        __syncthreads();
        sh[threadIdx.x] += t;
        __syncthreads();
    }
    if (i < N_NODES) g_rowptr[i] = sh[threadIdx.x] - v;          // exclusive
    if (threadIdx.x == SCAN_BLK - 1) g_blksum[blockIdx.x] = sh[SCAN_BLK - 1];
}

// single-block exclusive scan of the block sums
__global__ void k_scan2() {
    __shared__ int sh[1024];
    __shared__ int carry;
    int tid = threadIdx.x;
    if (tid == 0) carry = 0;
    __syncthreads();
    for (int base = 0; base < NBLK; base += 1024) {
        int i = base + tid;
        int v = (i < NBLK) ? g_blksum[i] : 0;
        sh[tid] = v;
        __syncthreads();
        for (int o = 1; o < 1024; o <<= 1) {
            int t = (tid >= o) ? sh[tid - o] : 0;
            __syncthreads();
            sh[tid] += t;
            __syncthreads();
        }
        if (i < NBLK) g_blksum[i] = sh[tid] - v + carry;
        __syncthreads();
        if (tid == 0) carry += sh[1023];
        __syncthreads();
    }
}

// finalize rowptr, init cursor, compute dinv
__global__ void k_scan3() {
    int i = blockIdx.x * blockDim.x + threadIdx.x;
    if (i < N_NODES) {
        int rp = g_rowptr[i] + g_blksum[i >> 8];
        g_rowptr[i] = rp;
        g_cursor[i] = rp;
        int c = g_cnt[i];
        g_dinv[i] = (c > 0) ? rsqrtf((float)c) : 0.0f;
    }
    if (i == 0) g_rowptr[N_NODES] = N_EDGES;
}

// counting-sort scatter: bucket edges by h
__global__ void k_scatter(const int* __restrict__ h, const int* __restrict__ t) {
    int e = blockIdx.x * blockDim.x + threadIdx.x;
    if (e >= N_EDGES) return;
    int hh = __ldg(h + e);
    int tt = __ldg(t + e);
    int slot = atomicAdd(&g_cursor[hh], 1);
    g_ts[slot] = tt;
    g_gs[slot] = g_dinv[hh] * g_dinv[tt];
}

// E0 = concat(user_emb, item_emb)
__global__ void k_init(const float* __restrict__ ue, const float* __restrict__ ie) {
    int i = blockIdx.x * blockDim.x + threadIdx.x;
    const int TOT = N_NODES * VEC;
    if (i >= TOT) return;
    const int UQ = N_USERS * VEC;
    float4 v = (i < UQ) ? __ldg(reinterpret_cast<const float4*>(ue) + i)
                        : __ldg(reinterpret_cast<const float4*>(ie) + (i - UQ));
    g_E0[i] = v;
}

// warp-per-row CSR SpMM, half-warp edge split:
// lanes 0-15 take even edges, lanes 16-31 odd edges; each lane gathers a float4
// (16 B). 4 edges per unrolled iteration with only 2 gather LDGs per lane.
// Final cross-half combine via 4x shfl_xor(16) once per row.
__global__ void __launch_bounds__(256) k_csr(int layer) {
    int wg   = (blockIdx.x * blockDim.x + threadIdx.x) >> 5;
    int lane = threadIdx.x & 31;
    if (wg >= N_NODES) return;
    int half = lane >> 4;        // 0 or 1
    int il   = lane & 15;        // float4 slot within row

    const float4* __restrict__ src = (layer == 0) ? g_E0 : g_E1;
    float4*       __restrict__ dst = (layer == 0) ? g_E1 : g_E2;

    int beg = g_rowptr[wg];
    int end = g_rowptr[wg + 1];
    float ax = 0.0f, ay = 0.0f, az = 0.0f, aw = 0.0f;

    int e = beg;
    // 4 edges per iteration: this lane handles e+half and e+2+half
    for (; e + 4 <= end; e += 4) {
        int   m0 = e + half,          m1 = e + 2 + half;
        int   t0 = __ldg(g_ts + m0);  int   t1 = __ldg(g_ts + m1);
        float w0 = __ldg(g_gs + m0);  float w1 = __ldg(g_gs + m1);
        float4 v0 = __ldg(&src[(size_t)t0 * VEC + il]);
        float4 v1 = __ldg(&src[(size_t)t1 * VEC + il]);
        ax += w0 * v0.x + w1 * v1.x;
        ay += w0 * v0.y + w1 * v1.y;
        az += w0 * v0.z + w1 * v1.z;
        aw += w0 * v0.w + w1 * v1.w;
    }
    // tail (0-3 edges): only half 0 contributes weight; half 1 loads same row (dedup'd)
    for (; e < end; ++e) {
        int   t0 = __ldg(g_ts + e);
        float w0 = (half == 0) ? __ldg(g_gs + e) : 0.0f;
        float4 v0 = __ldg(&src[(size_t)t0 * VEC + il]);
        ax += w0 * v0.x;
        ay += w0 * v0.y;
        az += w0 * v0.z;
        aw += w0 * v0.w;
    }

    // combine the two half-warp partial sums (once per row)
    ax += __shfl_xor_sync(0xFFFFFFFFu, ax, 16);
    ay += __shfl_xor_sync(0xFFFFFFFFu, ay, 16);
    az += __shfl_xor_sync(0xFFFFFFFFu, az, 16);
    aw += __shfl_xor_sync(0xFFFFFFFFu, aw, 16);

    if (half == 0) {
        size_t idx = (size_t)wg * VEC + il;
        float4 old = __ldg(&src[idx]);
        dst[idx] = make_float4(ax + old.x, ay + old.y, az + old.z, aw + old.w);
    }
}

// one warp per sample; acc row = E0 + E1 + E2 gathered on the fly
__global__ void k_loss(const float* __restrict__ ue, const float* __restrict__ ie,
                       const int* __restrict__ users, const int* __restrict__ pos,
                       const int* __restrict__ neg, float* __restrict__ out) {
    int warp = (blockIdx.x * blockDim.x + threadIdx.x) >> 5;
    int lane = threadIdx.x & 31;
    if (warp >= BATCH) return;
    int u = users[warp], p = pos[warp], n = neg[warp];

    const float2* e0 = reinterpret_cast<const float2*>(g_E0);
    const float2* e1 = reinterpret_cast<const float2*>(g_E1);
    const float2* e2 = reinterpret_cast<const float2*>(g_E2);

    size_t ui = (size_t)u * 32 + lane;
    size_t pi = (size_t)(N_USERS + p) * 32 + lane;
    size_t ni = (size_t)(N_USERS + n) * 32 + lane;

    float2 u0 = __ldg(e0 + ui), u1 = __ldg(e1 + ui), u2 = __ldg(e2 + ui);
    float2 p0 = __ldg(e0 + pi), p1 = __ldg(e1 + pi), p2 = __ldg(e2 + pi);
    float2 n0 = __ldg(e0 + ni), n1 = __ldg(e1 + ni), n2 = __ldg(e2 + ni);

    float2 uv = make_float2(u0.x + u1.x + u2.x, u0.y + u1.y + u2.y);
    float2 pv = make_float2(p0.x + p1.x + p2.x, p0.y + p1.y + p2.y);
    float2 nv = make_float2(n0.x + n1.x + n2.x, n0.y + n1.y + n2.y);
    float s = uv.x * (nv.x - pv.x) + uv.y * (nv.y - pv.y);   // neg - pos partial

    const float2* up = reinterpret_cast<const float2*>(ue + (size_t)u * EMB_DIM);
    const float2* pp = reinterpret_cast<const float2*>(ie + (size_t)p * EMB_DIM);
    const float2* np = reinterpret_cast<const float2*>(ie + (size_t)n * EMB_DIM);
    float2 a = __ldg(up + lane), b = __ldg(pp + lane), c = __ldg(np + lane);
    float r = a.x*a.x + a.y*a.y + b.x*b.x + b.y*b.y + c.x*c.x + c.y*c.y;

    #pragma unroll
    for (int o = 16; o; o >>= 1) {
        s += __shfl_xor_sync(0xFFFFFFFFu, s, o);
        r += __shfl_xor_sync(0xFFFFFFFFu, r, o);
    }
    if (lane == 0) {
        float x  = s;
        float sp = (x > 0.0f) ? x + log1pf(expf(-x)) : log1pf(expf(x));
        atomicAdd(&out[0], sp * (1.0f / BATCH));
        atomicAdd(&out[1], r * EMB_REG);
    }
}

// ---------------- launch ----------------
extern "C" void kernel_launch(void* const* d_in, const int* in_sizes, int n_in,
                              void* d_out, int out_size) {
    const float* ue    = (const float*)d_in[0];
    const float* ie    = (const float*)d_in[1];
    const int*   all_h = (const int*)  d_in[2];
    const int*   all_t = (const int*)  d_in[3];
    const int*   users = (const int*)  d_in[4];
    const int*   pos   = (const int*)  d_in[5];
    const int*   neg   = (const int*)  d_in[6];
    float*       out   = (float*)d_out;

    const int T = 256;
    const int gNode = (N_NODES + T - 1) / T;
    const int gEdge = (N_EDGES + T - 1) / T;
    const int gVec  = (N_NODES * VEC + T - 1) / T;
    const int gCsr  = ((N_NODES * 32) + T - 1) / T;   // warp per row

    k_zero   <<<gNode, T>>>(out);
    k_deg    <<<gEdge, T>>>(all_h);
    k_scan1  <<<NBLK, SCAN_BLK>>>();
    k_scan2  <<<1, 1024>>>();
    k_scan3  <<<gNode, T>>>();
    k_scatter<<<gEdge, T>>>(all_h, all_t);
    k_init   <<<gVec,  T>>>(ue, ie);

    k_csr<<<gCsr, T>>>(0);
    k_csr<<<gCsr, T>>>(1);

    k_loss<<<(BATCH * 32 + T - 1) / T, T>>>(ue, ie, users, pos, neg, out);
}

// round 13
// speedup vs baseline: 1.2939x; 1.0295x over previous
#include <cuda_runtime.h>
#include <math.h>

#define N_USERS 100000
#define N_ITEMS 200000
#define N_NODES 300000
#define EMB_DIM 64
#define VEC     16          // float4s per row
#define N_EDGES 4000000
#define BATCH   8192
#define EMB_REG 2.5e-05f
#define SCAN_BLK 256
#define NBLK ((N_NODES + SCAN_BLK - 1) / SCAN_BLK)   // 1172

// ---------------- scratch (device globals) ----------------
static __device__ int    g_cnt   [N_NODES];
static __device__ int    g_rowptr[N_NODES + 1];
static __device__ int    g_cursor[N_NODES];
static __device__ int    g_blksum[NBLK];
static __device__ float  g_dinv  [N_NODES];
static __device__ int2   g_edge  [N_EDGES];      // packed (t, w-as-int), sorted by h
static __device__ float4 g_E0 [(size_t)N_NODES * VEC];   // layer-0 (input) embeddings
static __device__ float4 g_E1 [(size_t)N_NODES * VEC];   // after layer 1
static __device__ float4 g_E2 [(size_t)N_NODES * VEC];   // after layer 2

// ---------------- kernels ----------------

__global__ void k_zero(float* out) {
    int i = blockIdx.x * blockDim.x + threadIdx.x;
    if (i < N_NODES) g_cnt[i] = 0;
    if (i < 2)       out[i]   = 0.0f;
}

__global__ void k_deg(const int* __restrict__ h) {
    int e = blockIdx.x * blockDim.x + threadIdx.x;
    if (e < N_EDGES) atomicAdd(&g_cnt[__ldg(h + e)], 1);
}

// block-local exclusive scan; block totals to g_blksum
__global__ void k_scan1() {
    __shared__ int sh[SCAN_BLK];
    int i = blockIdx.x * SCAN_BLK + threadIdx.x;
    int v = (i < N_NODES) ? g_cnt[i] : 0;
    sh[threadIdx.x] = v;
    __syncthreads();
    for (int o = 1; o < SCAN_BLK; o <<= 1) {
        int t = (threadIdx.x >= o) ? sh[threadIdx.x - o] : 0;
        __syncthreads();
        sh[threadIdx.x] += t;
        __syncthreads();
    }
    if (i < N_NODES) g_rowptr[i] = sh[threadIdx.x] - v;          // exclusive
    if (threadIdx.x == SCAN_BLK - 1) g_blksum[blockIdx.x] = sh[SCAN_BLK - 1];
}

// single-block exclusive scan of the block sums
__global__ void k_scan2() {
    __shared__ int sh[1024];
    __shared__ int carry;
    int tid = threadIdx.x;
    if (tid == 0) carry = 0;
    __syncthreads();
    for (int base = 0; base < NBLK; base += 1024) {
        int i = base + tid;
        int v = (i < NBLK) ? g_blksum[i] : 0;
        sh[tid] = v;
        __syncthreads();
        for (int o = 1; o < 1024; o <<= 1) {
            int t = (tid >= o) ? sh[tid - o] : 0;
            __syncthreads();
            sh[tid] += t;
            __syncthreads();
        }
        if (i < NBLK) g_blksum[i] = sh[tid] - v + carry;
        __syncthreads();
        if (tid == 0) carry += sh[1023];
        __syncthreads();
    }
}

// finalize rowptr, init cursor, compute dinv
__global__ void k_scan3() {
    int i = blockIdx.x * blockDim.x + threadIdx.x;
    if (i < N_NODES) {
        int rp = g_rowptr[i] + g_blksum[i >> 8];
        g_rowptr[i] = rp;
        g_cursor[i] = rp;
        int c = g_cnt[i];
        g_dinv[i] = (c > 0) ? rsqrtf((float)c) : 0.0f;
    }
    if (i == 0) g_rowptr[N_NODES] = N_EDGES;
}

// counting-sort scatter: bucket edges by h; single packed 8B store per edge
__global__ void k_scatter(const int* __restrict__ h, const int* __restrict__ t) {
    int e = blockIdx.x * blockDim.x + threadIdx.x;
    if (e >= N_EDGES) return;
    int hh = __ldg(h + e);
    int tt = __ldg(t + e);
    int slot = atomicAdd(&g_cursor[hh], 1);
    float w = g_dinv[hh] * g_dinv[tt];
    g_edge[slot] = make_int2(tt, __float_as_int(w));
}

// E0 = concat(user_emb, item_emb)
__global__ void k_init(const float* __restrict__ ue, const float* __restrict__ ie) {
    int i = blockIdx.x * blockDim.x + threadIdx.x;
    const int TOT = N_NODES * VEC;
    if (i >= TOT) return;
    const int UQ = N_USERS * VEC;
    float4 v = (i < UQ) ? __ldg(reinterpret_cast<const float4*>(ue) + i)
                        : __ldg(reinterpret_cast<const float4*>(ie) + (i - UQ));
    g_E0[i] = v;
}

// warp-per-row CSR SpMM, half-warp edge split, packed int2 descriptors:
// lanes 0-15 take even edges, lanes 16-31 odd edges; each lane gathers a float4.
// Per 4-edge iteration: 2 LDG.64 descriptor loads + 2 LDG.128 gathers per lane.
__global__ void __launch_bounds__(256) k_csr(int layer) {
    int wg   = (blockIdx.x * blockDim.x + threadIdx.x) >> 5;
    int lane = threadIdx.x & 31;
    if (wg >= N_NODES) return;
    int half = lane >> 4;        // 0 or 1
    int il   = lane & 15;        // float4 slot within row

    const float4* __restrict__ src = (layer == 0) ? g_E0 : g_E1;
    float4*       __restrict__ dst = (layer == 0) ? g_E1 : g_E2;

    int beg = g_rowptr[wg];
    int end = g_rowptr[wg + 1];
    float ax = 0.0f, ay = 0.0f, az = 0.0f, aw = 0.0f;

    int e = beg;
    // 4 edges per iteration: this lane handles e+half and e+2+half
    for (; e + 4 <= end; e += 4) {
        int2 d0 = __ldg(g_edge + e + half);
        int2 d1 = __ldg(g_edge + e + 2 + half);
        float4 v0 = __ldg(&src[(size_t)d0.x * VEC + il]);
        float4 v1 = __ldg(&src[(size_t)d1.x * VEC + il]);
        float w0 = __int_as_float(d0.y);
        float w1 = __int_as_float(d1.y);
        ax += w0 * v0.x + w1 * v1.x;
        ay += w0 * v0.y + w1 * v1.y;
        az += w0 * v0.z + w1 * v1.z;
        aw += w0 * v0.w + w1 * v1.w;
    }
    // tail (0-3 edges): only half 0 contributes weight; half 1 loads same row (dedup'd)
    for (; e < end; ++e) {
        int2 d0 = __ldg(g_edge + e);
        float w0 = (half == 0) ? __int_as_float(d0.y) : 0.0f;
        float4 v0 = __ldg(&src[(size_t)d0.x * VEC + il]);
        ax += w0 * v0.x;
        ay += w0 * v0.y;
        az += w0 * v0.z;
        aw += w0 * v0.w;
    }

    // combine the two half-warp partial sums (once per row)
    ax += __shfl_xor_sync(0xFFFFFFFFu, ax, 16);
    ay += __shfl_xor_sync(0xFFFFFFFFu, ay, 16);
    az += __shfl_xor_sync(0xFFFFFFFFu, az, 16);
    aw += __shfl_xor_sync(0xFFFFFFFFu, aw, 16);

    if (half == 0) {
        size_t idx = (size_t)wg * VEC + il;
        float4 old = __ldg(&src[idx]);
        dst[idx] = make_float4(ax + old.x, ay + old.y, az + old.z, aw + old.w);
    }
}

// one warp per sample; acc row = E0 + E1 + E2 gathered on the fly
__global__ void k_loss(const float* __restrict__ ue, const float* __restrict__ ie,
                       const int* __restrict__ users, const int* __restrict__ pos,
                       const int* __restrict__ neg, float* __restrict__ out) {
    int warp = (blockIdx.x * blockDim.x + threadIdx.x) >> 5;
    int lane = threadIdx.x & 31;
    if (warp >= BATCH) return;
    int u = users[warp], p = pos[warp], n = neg[warp];

    const float2* e0 = reinterpret_cast<const float2*>(g_E0);
    const float2* e1 = reinterpret_cast<const float2*>(g_E1);
    const float2* e2 = reinterpret_cast<const float2*>(g_E2);

    size_t ui = (size_t)u * 32 + lane;
    size_t pi = (size_t)(N_USERS + p) * 32 + lane;
    size_t ni = (size_t)(N_USERS + n) * 32 + lane;

    float2 u0 = __ldg(e0 + ui), u1 = __ldg(e1 + ui), u2 = __ldg(e2 + ui);
    float2 p0 = __ldg(e0 + pi), p1 = __ldg(e1 + pi), p2 = __ldg(e2 + pi);
    float2 n0 = __ldg(e0 + ni), n1 = __ldg(e1 + ni), n2 = __ldg(e2 + ni);

    float2 uv = make_float2(u0.x + u1.x + u2.x, u0.y + u1.y + u2.y);
    float2 pv = make_float2(p0.x + p1.x + p2.x, p0.y + p1.y + p2.y);
    float2 nv = make_float2(n0.x + n1.x + n2.x, n0.y + n1.y + n2.y);
    float s = uv.x * (nv.x - pv.x) + uv.y * (nv.y - pv.y);   // neg - pos partial

    const float2* up = reinterpret_cast<const float2*>(ue + (size_t)u * EMB_DIM);
    const float2* pp = reinterpret_cast<const float2*>(ie + (size_t)p * EMB_DIM);
    const float2* np = reinterpret_cast<const float2*>(ie + (size_t)n * EMB_DIM);
    float2 a = __ldg(up + lane), b = __ldg(pp + lane), c = __ldg(np + lane);
    float r = a.x*a.x + a.y*a.y + b.x*b.x + b.y*b.y + c.x*c.x + c.y*c.y;

    #pragma unroll
    for (int o = 16; o; o >>= 1) {
        s += __shfl_xor_sync(0xFFFFFFFFu, s, o);
        r += __shfl_xor_sync(0xFFFFFFFFu, r, o);
    }
    if (lane == 0) {
        float x  = s;
        float sp = (x > 0.0f) ? x + log1pf(expf(-x)) : log1pf(expf(x));
        atomicAdd(&out[0], sp * (1.0f / BATCH));
        atomicAdd(&out[1], r * EMB_REG);
    }
}

// ---------------- launch ----------------
extern "C" void kernel_launch(void* const* d_in, const int* in_sizes, int n_in,
                              void* d_out, int out_size) {
    const float* ue    = (const float*)d_in[0];
    const float* ie    = (const float*)d_in[1];
    const int*   all_h = (const int*)  d_in[2];
    const int*   all_t = (const int*)  d_in[3];
    const int*   users = (const int*)  d_in[4];
    const int*   pos   = (const int*)  d_in[5];
    const int*   neg   = (const int*)  d_in[6];
    float*       out   = (float*)d_out;

    const int T = 256;
    const int gNode = (N_NODES + T - 1) / T;
    const int gEdge = (N_EDGES + T - 1) / T;
    const int gVec  = (N_NODES * VEC + T - 1) / T;
    const int gCsr  = ((N_NODES * 32) + T - 1) / T;   // warp per row

    k_zero   <<<gNode, T>>>(out);
    k_deg    <<<gEdge, T>>>(all_h);
    k_scan1  <<<NBLK, SCAN_BLK>>>();
    k_scan2  <<<1, 1024>>>();
    k_scan3  <<<gNode, T>>>();
    k_scatter<<<gEdge, T>>>(all_h, all_t);
    k_init   <<<gVec,  T>>>(ue, ie);

    k_csr<<<gCsr, T>>>(0);
    k_csr<<<gCsr, T>>>(1);

    k_loss<<<(BATCH * 32 + T - 1) / T, T>>>(ue, ie, users, pos, neg, out);
}

// round 14
// speedup vs baseline: 1.3005x; 1.0052x over previous
#include <cuda_runtime.h>
#include <math.h>

#define N_USERS 100000
#define N_ITEMS 200000
#define N_NODES 300000
#define EMB_DIM 64
#define VEC     16          // float4s per row
#define N_EDGES 4000000
#define BATCH   8192
#define EMB_REG 2.5e-05f
#define SCAN_BLK 256
#define NBLK ((N_NODES + SCAN_BLK - 1) / SCAN_BLK)   // 1172

// ---------------- scratch (device globals) ----------------
static __device__ int    g_cnt   [N_NODES];
static __device__ int    g_rowptr[N_NODES + 1];
static __device__ int    g_cursor[N_NODES];
static __device__ int    g_blksum[NBLK];
static __device__ float  g_dinv  [N_NODES];
static __device__ int2   g_edge  [N_EDGES];      // packed (t, w-as-int), sorted by h
static __device__ float4 g_E0 [(size_t)N_NODES * VEC];   // layer-0 (input) embeddings
static __device__ float4 g_E1 [(size_t)N_NODES * VEC];   // after layer 1
static __device__ float4 g_E2 [(size_t)N_NODES * VEC];   // after layer 2

// ---------------- kernels ----------------

__global__ void k_zero(float* out) {
    int i = blockIdx.x * blockDim.x + threadIdx.x;
    if (i < N_NODES) g_cnt[i] = 0;
    if (i < 2)       out[i]   = 0.0f;
}

__global__ void k_deg(const int* __restrict__ h) {
    int e = blockIdx.x * blockDim.x + threadIdx.x;
    if (e < N_EDGES) atomicAdd(&g_cnt[__ldg(h + e)], 1);
}

// block-local exclusive scan; block totals to g_blksum
__global__ void k_scan1() {
    __shared__ int sh[SCAN_BLK];
    int i = blockIdx.x * SCAN_BLK + threadIdx.x;
    int v = (i < N_NODES) ? g_cnt[i] : 0;
    sh[threadIdx.x] = v;
    __syncthreads();
    for (int o = 1; o < SCAN_BLK; o <<= 1) {
        int t = (threadIdx.x >= o) ? sh[threadIdx.x - o] : 0;
        __syncthreads();
        sh[threadIdx.x] += t;
        __syncthreads();
    }
    if (i < N_NODES) g_rowptr[i] = sh[threadIdx.x] - v;          // exclusive
    if (threadIdx.x == SCAN_BLK - 1) g_blksum[blockIdx.x] = sh[SCAN_BLK - 1];
}

// single-block exclusive scan of the block sums
__global__ void k_scan2() {
    __shared__ int sh[1024];
    __shared__ int carry;
    int tid = threadIdx.x;
    if (tid == 0) carry = 0;
    __syncthreads();
    for (int base = 0; base < NBLK; base += 1024) {
        int i = base + tid;
        int v = (i < NBLK) ? g_blksum[i] : 0;
        sh[tid] = v;
        __syncthreads();
        for (int o = 1; o < 1024; o <<= 1) {
            int t = (tid >= o) ? sh[tid - o] : 0;
            __syncthreads();
            sh[tid] += t;
            __syncthreads();
        }
        if (i < NBLK) g_blksum[i] = sh[tid] - v + carry;
        __syncthreads();
        if (tid == 0) carry += sh[1023];
        __syncthreads();
    }
}

// finalize rowptr, init cursor, compute dinv
__global__ void k_scan3() {
    int i = blockIdx.x * blockDim.x + threadIdx.x;
    if (i < N_NODES) {
        int rp = g_rowptr[i] + g_blksum[i >> 8];
        g_rowptr[i] = rp;
        g_cursor[i] = rp;
        int c = g_cnt[i];
        g_dinv[i] = (c > 0) ? rsqrtf((float)c) : 0.0f;
    }
    if (i == 0) g_rowptr[N_NODES] = N_EDGES;
}

// FUSED: blocks [0, gEdge) scatter edges into CSR buckets;
//        blocks [gEdge, gEdge+gVec) stream-init E0 = concat(ue, ie).
// The two halves touch disjoint data, so the streaming copy overlaps the
// atomic/scatter-bound phase instead of serializing after it.
__global__ void k_scatter_init(const int* __restrict__ h, const int* __restrict__ t,
                               const float* __restrict__ ue, const float* __restrict__ ie,
                               int edgeBlocks) {
    if ((int)blockIdx.x < edgeBlocks) {
        int e = blockIdx.x * blockDim.x + threadIdx.x;
        if (e >= N_EDGES) return;
        int hh = __ldg(h + e);
        int tt = __ldg(t + e);
        int slot = atomicAdd(&g_cursor[hh], 1);
        float w = g_dinv[hh] * g_dinv[tt];
        g_edge[slot] = make_int2(tt, __float_as_int(w));
    } else {
        int i = (blockIdx.x - edgeBlocks) * blockDim.x + threadIdx.x;
        const int TOT = N_NODES * VEC;
        if (i >= TOT) return;
        const int UQ = N_USERS * VEC;
        float4 v = (i < UQ) ? __ldg(reinterpret_cast<const float4*>(ue) + i)
                            : __ldg(reinterpret_cast<const float4*>(ie) + (i - UQ));
        g_E0[i] = v;
    }
}

// warp-per-row CSR SpMM, half-warp edge split, packed int2 descriptors:
// lanes 0-15 take even edges, lanes 16-31 odd edges; each lane gathers a float4.
// Per 4-edge iteration: 2 LDG.64 descriptor loads + 2 LDG.128 gathers per lane.
__global__ void __launch_bounds__(256) k_csr(int layer) {
    int wg   = (blockIdx.x * blockDim.x + threadIdx.x) >> 5;
    int lane = threadIdx.x & 31;
    if (wg >= N_NODES) return;
    int half = lane >> 4;        // 0 or 1
    int il   = lane & 15;        // float4 slot within row

    const float4* __restrict__ src = (layer == 0) ? g_E0 : g_E1;
    float4*       __restrict__ dst = (layer == 0) ? g_E1 : g_E2;

    int beg = g_rowptr[wg];
    int end = g_rowptr[wg + 1];
    float ax = 0.0f, ay = 0.0f, az = 0.0f, aw = 0.0f;

    int e = beg;
    // 4 edges per iteration: this lane handles e+half and e+2+half
    for (; e + 4 <= end; e += 4) {
        int2 d0 = __ldg(g_edge + e + half);
        int2 d1 = __ldg(g_edge + e + 2 + half);
        float4 v0 = __ldg(&src[(size_t)d0.x * VEC + il]);
        float4 v1 = __ldg(&src[(size_t)d1.x * VEC + il]);
        float w0 = __int_as_float(d0.y);
        float w1 = __int_as_float(d1.y);
        ax += w0 * v0.x + w1 * v1.x;
        ay += w0 * v0.y + w1 * v1.y;
        az += w0 * v0.z + w1 * v1.z;
        aw += w0 * v0.w + w1 * v1.w;
    }
    // tail (0-3 edges): only half 0 contributes weight; half 1 loads same row (dedup'd)
    for (; e < end; ++e) {
        int2 d0 = __ldg(g_edge + e);
        float w0 = (half == 0) ? __int_as_float(d0.y) : 0.0f;
        float4 v0 = __ldg(&src[(size_t)d0.x * VEC + il]);
        ax += w0 * v0.x;
        ay += w0 * v0.y;
        az += w0 * v0.z;
        aw += w0 * v0.w;
    }

    // combine the two half-warp partial sums (once per row)
    ax += __shfl_xor_sync(0xFFFFFFFFu, ax, 16);
    ay += __shfl_xor_sync(0xFFFFFFFFu, ay, 16);
    az += __shfl_xor_sync(0xFFFFFFFFu, az, 16);
    aw += __shfl_xor_sync(0xFFFFFFFFu, aw, 16);

    if (half == 0) {
        size_t idx = (size_t)wg * VEC + il;
        float4 old = __ldg(&src[idx]);
        dst[idx] = make_float4(ax + old.x, ay + old.y, az + old.z, aw + old.w);
    }
}

// one warp per sample; acc row = E0 + E1 + E2 gathered on the fly
__global__ void k_loss(const float* __restrict__ ue, const float* __restrict__ ie,
                       const int* __restrict__ users, const int* __restrict__ pos,
                       const int* __restrict__ neg, float* __restrict__ out) {
    int warp = (blockIdx.x * blockDim.x + threadIdx.x) >> 5;
    int lane = threadIdx.x & 31;
    if (warp >= BATCH) return;
    int u = users[warp], p = pos[warp], n = neg[warp];

    const float2* e0 = reinterpret_cast<const float2*>(g_E0);
    const float2* e1 = reinterpret_cast<const float2*>(g_E1);
    const float2* e2 = reinterpret_cast<const float2*>(g_E2);

    size_t ui = (size_t)u * 32 + lane;
    size_t pi = (size_t)(N_USERS + p) * 32 + lane;
    size_t ni = (size_t)(N_USERS + n) * 32 + lane;

    float2 u0 = __ldg(e0 + ui), u1 = __ldg(e1 + ui), u2 = __ldg(e2 + ui);
    float2 p0 = __ldg(e0 + pi), p1 = __ldg(e1 + pi), p2 = __ldg(e2 + pi);
    float2 n0 = __ldg(e0 + ni), n1 = __ldg(e1 + ni), n2 = __ldg(e2 + ni);

    float2 uv = make_float2(u0.x + u1.x + u2.x, u0.y + u1.y + u2.y);
    float2 pv = make_float2(p0.x + p1.x + p2.x, p0.y + p1.y + p2.y);
    float2 nv = make_float2(n0.x + n1.x + n2.x, n0.y + n1.y + n2.y);
    float s = uv.x * (nv.x - pv.x) + uv.y * (nv.y - pv.y);   // neg - pos partial

    const float2* up = reinterpret_cast<const float2*>(ue + (size_t)u * EMB_DIM);
    const float2* pp = reinterpret_cast<const float2*>(ie + (size_t)p * EMB_DIM);
    const float2* np = reinterpret_cast<const float2*>(ie + (size_t)n * EMB_DIM);
    float2 a = __ldg(up + lane), b = __ldg(pp + lane), c = __ldg(np + lane);
    float r = a.x*a.x + a.y*a.y + b.x*b.x + b.y*b.y + c.x*c.x + c.y*c.y;

    #pragma unroll
    for (int o = 16; o; o >>= 1) {
        s += __shfl_xor_sync(0xFFFFFFFFu, s, o);
        r += __shfl_xor_sync(0xFFFFFFFFu, r, o);
    }
    if (lane == 0) {
        float x  = s;
        float sp = (x > 0.0f) ? x + log1pf(expf(-x)) : log1pf(expf(x));
        atomicAdd(&out[0], sp * (1.0f / BATCH));
        atomicAdd(&out[1], r * EMB_REG);
    }
}

// ---------------- launch ----------------
extern "C" void kernel_launch(void* const* d_in, const int* in_sizes, int n_in,
                              void* d_out, int out_size) {
    const float* ue    = (const float*)d_in[0];
    const float* ie    = (const float*)d_in[1];
    const int*   all_h = (const int*)  d_in[2];
    const int*   all_t = (const int*)  d_in[3];
    const int*   users = (const int*)  d_in[4];
    const int*   pos   = (const int*)  d_in[5];
    const int*   neg   = (const int*)  d_in[6];
    float*       out   = (float*)d_out;

    const int T = 256;
    const int gNode = (N_NODES + T - 1) / T;
    const int gEdge = (N_EDGES + T - 1) / T;
    const int gVec  = (N_NODES * VEC + T - 1) / T;
    const int gCsr  = ((N_NODES * 32) + T - 1) / T;   // warp per row

    k_zero        <<<gNode, T>>>(out);
    k_deg         <<<gEdge, T>>>(all_h);
    k_scan1       <<<NBLK, SCAN_BLK>>>();
    k_scan2       <<<1, 1024>>>();
    k_scan3       <<<gNode, T>>>();
    k_scatter_init<<<gEdge + gVec, T>>>(all_h, all_t, ue, ie, gEdge);

    k_csr<<<gCsr, T>>>(0);
    k_csr<<<gCsr, T>>>(1);

    k_loss<<<(BATCH * 32 + T - 1) / T, T>>>(ue, ie, users, pos, neg, out);
}

// round 16
// speedup vs baseline: 1.3819x; 1.0626x over previous
#include <cuda_runtime.h>
#include <math.h>

#define N_USERS 100000
#define N_ITEMS 200000
#define N_NODES 300000
#define EMB_DIM 64
#define VEC     16          // float4s per row
#define N_EDGES 4000000
#define BATCH   8192
#define NEEDED  (3 * BATCH)  // max distinct nodes needed for layer 2
#define EMB_REG 2.5e-05f
#define SCAN_BLK 256
#define NBLK ((N_NODES + SCAN_BLK - 1) / SCAN_BLK)   // 1172

// ---------------- scratch (device globals) ----------------
static __device__ int    g_cnt   [N_NODES];
static __device__ int    g_rowptr[N_NODES + 1];
static __device__ int    g_cursor[N_NODES];
static __device__ int    g_blksum[NBLK];
static __device__ float  g_dinv  [N_NODES];
static __device__ int2   g_edge  [N_EDGES];      // packed (t, w-as-int), sorted by h
static __device__ int    g_flag  [N_NODES];      // membership flag for layer-2 pruning
static __device__ int    g_nlist [NEEDED];       // compacted needed-node list
static __device__ int    g_ncnt;                 // count of needed nodes
static __device__ float4 g_E0 [(size_t)N_NODES * VEC];   // layer-0 (input) embeddings
static __device__ float4 g_E1 [(size_t)N_NODES * VEC];   // after layer 1 (full)
static __device__ float4 g_E2 [(size_t)N_NODES * VEC];   // after layer 2 (batch rows only)

// ---------------- kernels ----------------

__global__ void k_zero(float* out) {
    int i = blockIdx.x * blockDim.x + threadIdx.x;
    if (i < N_NODES) { g_cnt[i] = 0; g_flag[i] = 0; }
    if (i == 0) g_ncnt = 0;
    if (i < 2)  out[i] = 0.0f;
}

__global__ void k_deg(const int* __restrict__ h) {
    int e = blockIdx.x * blockDim.x + threadIdx.x;
    if (e < N_EDGES) atomicAdd(&g_cnt[__ldg(h + e)], 1);
}

// block-local exclusive scan; block totals to g_blksum
__global__ void k_scan1() {
    __shared__ int sh[SCAN_BLK];
    int i = blockIdx.x * SCAN_BLK + threadIdx.x;
    int v = (i < N_NODES) ? g_cnt[i] : 0;
    sh[threadIdx.x] = v;
    __syncthreads();
    for (int o = 1; o < SCAN_BLK; o <<= 1) {
        int t = (threadIdx.x >= o) ? sh[threadIdx.x - o] : 0;
        __syncthreads();
        sh[threadIdx.x] += t;
        __syncthreads();
    }
    if (i < N_NODES) g_rowptr[i] = sh[threadIdx.x] - v;          // exclusive
    if (threadIdx.x == SCAN_BLK - 1) g_blksum[blockIdx.x] = sh[SCAN_BLK - 1];
}

// single-block exclusive scan of the block sums
__global__ void k_scan2() {
    __shared__ int sh[1024];
    __shared__ int carry;
    int tid = threadIdx.x;
    if (tid == 0) carry = 0;
    __syncthreads();
    for (int base = 0; base < NBLK; base += 1024) {
        int i = base + tid;
        int v = (i < NBLK) ? g_blksum[i] : 0;
        sh[tid] = v;
        __syncthreads();
        for (int o = 1; o < 1024; o <<= 1) {
            int t = (tid >= o) ? sh[tid - o] : 0;
            __syncthreads();
            sh[tid] += t;
            __syncthreads();
        }
        if (i < NBLK) g_blksum[i] = sh[tid] - v + carry;
        __syncthreads();
        if (tid == 0) carry += sh[1023];
        __syncthreads();
    }
}

// finalize rowptr, init cursor, compute dinv
__global__ void k_scan3() {
    int i = blockIdx.x * blockDim.x + threadIdx.x;
    if (i < N_NODES) {
        int rp = g_rowptr[i] + g_blksum[i >> 8];
        g_rowptr[i] = rp;
        g_cursor[i] = rp;
        int c = g_cnt[i];
        g_dinv[i] = (c > 0) ? rsqrtf((float)c) : 0.0f;
    }
    if (i == 0) g_rowptr[N_NODES] = N_EDGES;
}

// FUSED: blocks [0, gEdge)                scatter edges into CSR buckets
//        blocks [gEdge, gEdge+gVec)       stream-init E0 = concat(ue, ie)
//        blocks [gEdge+gVec, +gMark)      mark + compact the layer-2 needed set
__global__ void k_scatter_init(const int* __restrict__ h, const int* __restrict__ t,
                               const float* __restrict__ ue, const float* __restrict__ ie,
                               const int* __restrict__ users, const int* __restrict__ pos,
                               const int* __restrict__ neg,
                               int edgeBlocks, int vecBlocks) {
    int b = (int)blockIdx.x;
    if (b < edgeBlocks) {
        int e = b * blockDim.x + threadIdx.x;
        if (e >= N_EDGES) return;
        int hh = __ldg(h + e);
        int tt = __ldg(t + e);
        int slot = atomicAdd(&g_cursor[hh], 1);
        float w = g_dinv[hh] * g_dinv[tt];
        g_edge[slot] = make_int2(tt, __float_as_int(w));
    } else if (b < edgeBlocks + vecBlocks) {
        int i = (b - edgeBlocks) * blockDim.x + threadIdx.x;
        const int TOT = N_NODES * VEC;
        if (i >= TOT) return;
        const int UQ = N_USERS * VEC;
        float4 v = (i < UQ) ? __ldg(reinterpret_cast<const float4*>(ue) + i)
                            : __ldg(reinterpret_cast<const float4*>(ie) + (i - UQ));
        g_E0[i] = v;
    } else {
        int i = (b - edgeBlocks - vecBlocks) * blockDim.x + threadIdx.x;
        if (i >= NEEDED) return;
        int node;
        if (i < BATCH)           node = __ldg(users + i);
        else if (i < 2 * BATCH)  node = N_USERS + __ldg(pos + (i - BATCH));
        else                     node = N_USERS + __ldg(neg + (i - 2 * BATCH));
        if (atomicExch(&g_flag[node], 1) == 0) {
            int slot = atomicAdd(&g_ncnt, 1);
            g_nlist[slot] = node;
        }
    }
}

// layer-1 CSR SpMM over ALL rows: half-warp edge split, packed int2 descriptors.
__global__ void __launch_bounds__(256) k_csr1() {
    int wg   = (blockIdx.x * blockDim.x + threadIdx.x) >> 5;
    int lane = threadIdx.x & 31;
    if (wg >= N_NODES) return;
    int half = lane >> 4;
    int il   = lane & 15;

    const float4* __restrict__ src = g_E0;
    float4*       __restrict__ dst = g_E1;

    int beg = g_rowptr[wg];
    int end = g_rowptr[wg + 1];
    float ax = 0.0f, ay = 0.0f, az = 0.0f, aw = 0.0f;

    int e = beg;
    for (; e + 4 <= end; e += 4) {
        int2 d0 = __ldg(g_edge + e + half);
        int2 d1 = __ldg(g_edge + e + 2 + half);
        float4 v0 = __ldg(&src[(size_t)d0.x * VEC + il]);
        float4 v1 = __ldg(&src[(size_t)d1.x * VEC + il]);
        float w0 = __int_as_float(d0.y);
        float w1 = __int_as_float(d1.y);
        ax += w0 * v0.x + w1 * v1.x;
        ay += w0 * v0.y + w1 * v1.y;
        az += w0 * v0.z + w1 * v1.z;
        aw += w0 * v0.w + w1 * v1.w;
    }
    for (; e < end; ++e) {
        int2 d0 = __ldg(g_edge + e);
        float w0 = (half == 0) ? __int_as_float(d0.y) : 0.0f;
        float4 v0 = __ldg(&src[(size_t)d0.x * VEC + il]);
        ax += w0 * v0.x;
        ay += w0 * v0.y;
        az += w0 * v0.z;
        aw += w0 * v0.w;
    }

    ax += __shfl_xor_sync(0xFFFFFFFFu, ax, 16);
    ay += __shfl_xor_sync(0xFFFFFFFFu, ay, 16);
    az += __shfl_xor_sync(0xFFFFFFFFu, az, 16);
    aw += __shfl_xor_sync(0xFFFFFFFFu, aw, 16);

    if (half == 0) {
        size_t idx = (size_t)wg * VEC + il;
        float4 old = __ldg(&src[idx]);
        dst[idx] = make_float4(ax + old.x, ay + old.y, az + old.z, aw + old.w);
    }
}

// layer-2 CSR SpMM over ONLY the compacted needed rows (<= NEEDED).
__global__ void __launch_bounds__(256) k_csr2() {
    int wi   = (blockIdx.x * blockDim.x + threadIdx.x) >> 5;
    int lane = threadIdx.x & 31;
    if (wi >= g_ncnt) return;
    int wg = g_nlist[wi];
    int half = lane >> 4;
    int il   = lane & 15;

    const float4* __restrict__ src = g_E1;
    float4*       __restrict__ dst = g_E2;

    int beg = g_rowptr[wg];
    int end = g_rowptr[wg + 1];
    float ax = 0.0f, ay = 0.0f, az = 0.0f, aw = 0.0f;

    int e = beg;
    for (; e + 4 <= end; e += 4) {
        int2 d0 = __ldg(g_edge + e + half);
        int2 d1 = __ldg(g_edge + e + 2 + half);
        float4 v0 = __ldg(&src[(size_t)d0.x * VEC + il]);
        float4 v1 = __ldg(&src[(size_t)d1.x * VEC + il]);
        float w0 = __int_as_float(d0.y);
        float w1 = __int_as_float(d1.y);
        ax += w0 * v0.x + w1 * v1.x;
        ay += w0 * v0.y + w1 * v1.y;
        az += w0 * v0.z + w1 * v1.z;
        aw += w0 * v0.w + w1 * v1.w;
    }
    for (; e < end; ++e) {
        int2 d0 = __ldg(g_edge + e);
        float w0 = (half == 0) ? __int_as_float(d0.y) : 0.0f;
        float4 v0 = __ldg(&src[(size_t)d0.x * VEC + il]);
        ax += w0 * v0.x;
        ay += w0 * v0.y;
        az += w0 * v0.z;
        aw += w0 * v0.w;
    }

    ax += __shfl_xor_sync(0xFFFFFFFFu, ax, 16);
    ay += __shfl_xor_sync(0xFFFFFFFFu, ay, 16);
    az += __shfl_xor_sync(0xFFFFFFFFu, az, 16);
    aw += __shfl_xor_sync(0xFFFFFFFFu, aw, 16);

    if (half == 0) {
        size_t idx = (size_t)wg * VEC + il;
        float4 old = __ldg(&src[idx]);
        dst[idx] = make_float4(ax + old.x, ay + old.y, az + old.z, aw + old.w);
    }
}

// one warp per sample; acc row = E0 + E1 + E2 gathered on the fly
__global__ void k_loss(const float* __restrict__ ue, const float* __restrict__ ie,
                       const int* __restrict__ users, const int* __restrict__ pos,
                       const int* __restrict__ neg, float* __restrict__ out) {
    int warp = (blockIdx.x * blockDim.x + threadIdx.x) >> 5;
    int lane = threadIdx.x & 31;
    if (warp >= BATCH) return;
    int u = users[warp], p = pos[warp], n = neg[warp];

    const float2* e0 = reinterpret_cast<const float2*>(g_E0);
    const float2* e1 = reinterpret_cast<const float2*>(g_E1);
    const float2* e2 = reinterpret_cast<const float2*>(g_E2);

    size_t ui = (size_t)u * 32 + lane;
    size_t pi = (size_t)(N_USERS + p) * 32 + lane;
    size_t ni = (size_t)(N_USERS + n) * 32 + lane;

    float2 u0 = __ldg(e0 + ui), u1 = __ldg(e1 + ui), u2 = __ldg(e2 + ui);
    float2 p0 = __ldg(e0 + pi), p1 = __ldg(e1 + pi), p2 = __ldg(e2 + pi);
    float2 n0 = __ldg(e0 + ni), n1 = __ldg(e1 + ni), n2 = __ldg(e2 + ni);

    float2 uv = make_float2(u0.x + u1.x + u2.x, u0.y + u1.y + u2.y);
    float2 pv = make_float2(p0.x + p1.x + p2.x, p0.y + p1.y + p2.y);
    float2 nv = make_float2(n0.x + n1.x + n2.x, n0.y + n1.y + n2.y);
    float s = uv.x * (nv.x - pv.x) + uv.y * (nv.y - pv.y);   // neg - pos partial

    const float2* up = reinterpret_cast<const float2*>(ue + (size_t)u * EMB_DIM);
    const float2* pp = reinterpret_cast<const float2*>(ie + (size_t)p * EMB_DIM);
    const float2* np = reinterpret_cast<const float2*>(ie + (size_t)n * EMB_DIM);
    float2 a = __ldg(up + lane), b = __ldg(pp + lane), c = __ldg(np + lane);
    float r = a.x*a.x + a.y*a.y + b.x*b.x + b.y*b.y + c.x*c.x + c.y*c.y;

    #pragma unroll
    for (int o = 16; o; o >>= 1) {
        s += __shfl_xor_sync(0xFFFFFFFFu, s, o);
        r += __shfl_xor_sync(0xFFFFFFFFu, r, o);
    }
    if (lane == 0) {
        float x  = s;
        float sp = (x > 0.0f) ? x + log1pf(expf(-x)) : log1pf(expf(x));
        atomicAdd(&out[0], sp * (1.0f / BATCH));
        atomicAdd(&out[1], r * EMB_REG);
    }
}

// ---------------- launch ----------------
extern "C" void kernel_launch(void* const* d_in, const int* in_sizes, int n_in,
                              void* d_out, int out_size) {
    const float* ue    = (const float*)d_in[0];
    const float* ie    = (const float*)d_in[1];
    const int*   all_h = (const int*)  d_in[2];
    const int*   all_t = (const int*)  d_in[3];
    const int*   users = (const int*)  d_in[4];
    const int*   pos   = (const int*)  d_in[5];
    const int*   neg   = (const int*)  d_in[6];
    float*       out   = (float*)d_out;

    const int T = 256;
    const int gNode = (N_NODES + T - 1) / T;
    const int gEdge = (N_EDGES + T - 1) / T;
    const int gVec  = (N_NODES * VEC + T - 1) / T;
    const int gMark = (NEEDED + T - 1) / T;
    const int gCsr1 = ((N_NODES * 32) + T - 1) / T;   // warp per row, all rows
    const int gCsr2 = ((NEEDED  * 32) + T - 1) / T;   // warp per needed row

    k_zero        <<<gNode, T>>>(out);
    k_deg         <<<gEdge, T>>>(all_h);
    k_scan1       <<<NBLK, SCAN_BLK>>>();
    k_scan2       <<<1, 1024>>>();
    k_scan3       <<<gNode, T>>>();
    k_scatter_init<<<gEdge + gVec + gMark, T>>>(all_h, all_t, ue, ie,
                                                users, pos, neg, gEdge, gVec);

    k_csr1<<<gCsr1, T>>>();
    k_csr2<<<gCsr2, T>>>();

    k_loss<<<(BATCH * 32 + T - 1) / T, T>>>(ue, ie, users, pos, neg, out);
}

// round 17
// speedup vs baseline: 1.7256x; 1.2487x over previous
#include <cuda_runtime.h>
#include <math.h>

#define N_USERS 100000
#define N_ITEMS 200000
#define N_NODES 300000
#define EMB_DIM 64
#define VEC     16          // float4s per row
#define N_EDGES 4000000
#define BATCH   8192
#define NEEDED  (3 * BATCH)  // max distinct nodes needed for layer 2
#define EMB_REG 2.5e-05f
#define SCAN_BLK 256
#define NBLK ((N_NODES + SCAN_BLK - 1) / SCAN_BLK)   // 1172

// ---------------- scratch (device globals) ----------------
static __device__ int    g_cnt   [N_NODES];
static __device__ int    g_rowptr[N_NODES + 1];
static __device__ int    g_cursor[N_NODES];
static __device__ int    g_blksum[NBLK];
static __device__ float  g_dinv  [N_NODES];
static __device__ int2   g_edge  [N_EDGES];      // packed (t, w-as-int), sorted by h
static __device__ int    g_flag  [N_NODES];      // membership flag: layer-2 needed set
static __device__ int    g_nlist [NEEDED];       // compacted needed-node list
static __device__ int    g_ncnt;                 // count of needed nodes
static __device__ int    g_flag1 [N_NODES];      // membership flag: layer-1 closure
static __device__ int    g_nlist1[N_NODES];      // compacted closure list
static __device__ int    g_ncnt1;                // count of closure nodes
static __device__ float4 g_E0 [(size_t)N_NODES * VEC];   // layer-0 (input) embeddings
static __device__ float4 g_E1 [(size_t)N_NODES * VEC];   // after layer 1 (closure rows)
static __device__ float4 g_E2 [(size_t)N_NODES * VEC];   // after layer 2 (batch rows)

// ---------------- kernels ----------------

__global__ void k_zero(float* out) {
    int i = blockIdx.x * blockDim.x + threadIdx.x;
    if (i < N_NODES) { g_cnt[i] = 0; g_flag[i] = 0; g_flag1[i] = 0; }
    if (i == 0) { g_ncnt = 0; g_ncnt1 = 0; }
    if (i < 2)  out[i] = 0.0f;
}

__global__ void k_deg(const int* __restrict__ h) {
    int e = blockIdx.x * blockDim.x + threadIdx.x;
    if (e < N_EDGES) atomicAdd(&g_cnt[__ldg(h + e)], 1);
}

// block-local exclusive scan; block totals to g_blksum
__global__ void k_scan1() {
    __shared__ int sh[SCAN_BLK];
    int i = blockIdx.x * SCAN_BLK + threadIdx.x;
    int v = (i < N_NODES) ? g_cnt[i] : 0;
    sh[threadIdx.x] = v;
    __syncthreads();
    for (int o = 1; o < SCAN_BLK; o <<= 1) {
        int t = (threadIdx.x >= o) ? sh[threadIdx.x - o] : 0;
        __syncthreads();
        sh[threadIdx.x] += t;
        __syncthreads();
    }
    if (i < N_NODES) g_rowptr[i] = sh[threadIdx.x] - v;          // exclusive
    if (threadIdx.x == SCAN_BLK - 1) g_blksum[blockIdx.x] = sh[SCAN_BLK - 1];
}

// single-block exclusive scan of the block sums
__global__ void k_scan2() {
    __shared__ int sh[1024];
    __shared__ int carry;
    int tid = threadIdx.x;
    if (tid == 0) carry = 0;
    __syncthreads();
    for (int base = 0; base < NBLK; base += 1024) {
        int i = base + tid;
        int v = (i < NBLK) ? g_blksum[i] : 0;
        sh[tid] = v;
        __syncthreads();
        for (int o = 1; o < 1024; o <<= 1) {
            int t = (tid >= o) ? sh[tid - o] : 0;
            __syncthreads();
            sh[tid] += t;
            __syncthreads();
        }
        if (i < NBLK) g_blksum[i] = sh[tid] - v + carry;
        __syncthreads();
        if (tid == 0) carry += sh[1023];
        __syncthreads();
    }
}

// finalize rowptr, init cursor, compute dinv
__global__ void k_scan3() {
    int i = blockIdx.x * blockDim.x + threadIdx.x;
    if (i < N_NODES) {
        int rp = g_rowptr[i] + g_blksum[i >> 8];
        g_rowptr[i] = rp;
        g_cursor[i] = rp;
        int c = g_cnt[i];
        g_dinv[i] = (c > 0) ? rsqrtf((float)c) : 0.0f;
    }
    if (i == 0) g_rowptr[N_NODES] = N_EDGES;
}

// FUSED: blocks [0, gEdge)                scatter edges into CSR buckets
//        blocks [gEdge, gEdge+gVec)       stream-init E0 = concat(ue, ie)
//        blocks [gEdge+gVec, +gMark)      mark + compact the layer-2 needed set
__global__ void k_scatter_init(const int* __restrict__ h, const int* __restrict__ t,
                               const float* __restrict__ ue, const float* __restrict__ ie,
                               const int* __restrict__ users, const int* __restrict__ pos,
                               const int* __restrict__ neg,
                               int edgeBlocks, int vecBlocks) {
    int b = (int)blockIdx.x;
    if (b < edgeBlocks) {
        int e = b * blockDim.x + threadIdx.x;
        if (e >= N_EDGES) return;
        int hh = __ldg(h + e);
        int tt = __ldg(t + e);
        int slot = atomicAdd(&g_cursor[hh], 1);
        float w = g_dinv[hh] * g_dinv[tt];
        g_edge[slot] = make_int2(tt, __float_as_int(w));
    } else if (b < edgeBlocks + vecBlocks) {
        int i = (b - edgeBlocks) * blockDim.x + threadIdx.x;
        const int TOT = N_NODES * VEC;
        if (i >= TOT) return;
        const int UQ = N_USERS * VEC;
        float4 v = (i < UQ) ? __ldg(reinterpret_cast<const float4*>(ue) + i)
                            : __ldg(reinterpret_cast<const float4*>(ie) + (i - UQ));
        g_E0[i] = v;
    } else {
        int i = (b - edgeBlocks - vecBlocks) * blockDim.x + threadIdx.x;
        if (i >= NEEDED) return;
        int node;
        if (i < BATCH)           node = __ldg(users + i);
        else if (i < 2 * BATCH)  node = N_USERS + __ldg(pos + (i - BATCH));
        else                     node = N_USERS + __ldg(neg + (i - 2 * BATCH));
        if (atomicExch(&g_flag[node], 1) == 0) {
            int slot = atomicAdd(&g_ncnt, 1);
            g_nlist[slot] = node;
        }
    }
}

// mark layer-1 closure: needed rows + their CSR neighbors. warp per needed row.
__global__ void k_mark1() {
    int wi   = (blockIdx.x * blockDim.x + threadIdx.x) >> 5;
    int lane = threadIdx.x & 31;
    if (wi >= g_ncnt) return;
    int row = g_nlist[wi];
    if (lane == 0) {
        if (atomicExch(&g_flag1[row], 1) == 0) {
            int slot = atomicAdd(&g_ncnt1, 1);
            g_nlist1[slot] = row;
        }
    }
    int beg = g_rowptr[row];
    int end = g_rowptr[row + 1];
    for (int e = beg + lane; e < end; e += 32) {
        int tt = __ldg(&g_edge[e].x);
        if (atomicExch(&g_flag1[tt], 1) == 0) {
            int slot = atomicAdd(&g_ncnt1, 1);
            g_nlist1[slot] = tt;
        }
    }
}

// layer-1 CSR SpMM over the compacted closure rows only.
__global__ void __launch_bounds__(256) k_csr1() {
    int wi   = (blockIdx.x * blockDim.x + threadIdx.x) >> 5;
    int lane = threadIdx.x & 31;
    if (wi >= g_ncnt1) return;
    int wg = g_nlist1[wi];
    int half = lane >> 4;
    int il   = lane & 15;

    const float4* __restrict__ src = g_E0;
    float4*       __restrict__ dst = g_E1;

    int beg = g_rowptr[wg];
    int end = g_rowptr[wg + 1];
    float ax = 0.0f, ay = 0.0f, az = 0.0f, aw = 0.0f;

    int e = beg;
    for (; e + 4 <= end; e += 4) {
        int2 d0 = __ldg(g_edge + e + half);
        int2 d1 = __ldg(g_edge + e + 2 + half);
        float4 v0 = __ldg(&src[(size_t)d0.x * VEC + il]);
        float4 v1 = __ldg(&src[(size_t)d1.x * VEC + il]);
        float w0 = __int_as_float(d0.y);
        float w1 = __int_as_float(d1.y);
        ax += w0 * v0.x + w1 * v1.x;
        ay += w0 * v0.y + w1 * v1.y;
        az += w0 * v0.z + w1 * v1.z;
        aw += w0 * v0.w + w1 * v1.w;
    }
    for (; e < end; ++e) {
        int2 d0 = __ldg(g_edge + e);
        float w0 = (half == 0) ? __int_as_float(d0.y) : 0.0f;
        float4 v0 = __ldg(&src[(size_t)d0.x * VEC + il]);
        ax += w0 * v0.x;
        ay += w0 * v0.y;
        az += w0 * v0.z;
        aw += w0 * v0.w;
    }

    ax += __shfl_xor_sync(0xFFFFFFFFu, ax, 16);
    ay += __shfl_xor_sync(0xFFFFFFFFu, ay, 16);
    az += __shfl_xor_sync(0xFFFFFFFFu, az, 16);
    aw += __shfl_xor_sync(0xFFFFFFFFu, aw, 16);

    if (half == 0) {
        size_t idx = (size_t)wg * VEC + il;
        float4 old = __ldg(&src[idx]);
        dst[idx] = make_float4(ax + old.x, ay + old.y, az + old.z, aw + old.w);
    }
}

// layer-2 CSR SpMM over ONLY the compacted needed rows (<= NEEDED).
__global__ void __launch_bounds__(256) k_csr2() {
    int wi   = (blockIdx.x * blockDim.x + threadIdx.x) >> 5;
    int lane = threadIdx.x & 31;
    if (wi >= g_ncnt) return;
    int wg = g_nlist[wi];
    int half = lane >> 4;
    int il   = lane & 15;

    const float4* __restrict__ src = g_E1;
    float4*       __restrict__ dst = g_E2;

    int beg = g_rowptr[wg];
    int end = g_rowptr[wg + 1];
    float ax = 0.0f, ay = 0.0f, az = 0.0f, aw = 0.0f;

    int e = beg;
    for (; e + 4 <= end; e += 4) {
        int2 d0 = __ldg(g_edge + e + half);
        int2 d1 = __ldg(g_edge + e + 2 + half);
        float4 v0 = __ldg(&src[(size_t)d0.x * VEC + il]);
        float4 v1 = __ldg(&src[(size_t)d1.x * VEC + il]);
        float w0 = __int_as_float(d0.y);
        float w1 = __int_as_float(d1.y);
        ax += w0 * v0.x + w1 * v1.x;
        ay += w0 * v0.y + w1 * v1.y;
        az += w0 * v0.z + w1 * v1.z;
        aw += w0 * v0.w + w1 * v1.w;
    }
    for (; e < end; ++e) {
        int2 d0 = __ldg(g_edge + e);
        float w0 = (half == 0) ? __int_as_float(d0.y) : 0.0f;
        float4 v0 = __ldg(&src[(size_t)d0.x * VEC + il]);
        ax += w0 * v0.x;
        ay += w0 * v0.y;
        az += w0 * v0.z;
        aw += w0 * v0.w;
    }

    ax += __shfl_xor_sync(0xFFFFFFFFu, ax, 16);
    ay += __shfl_xor_sync(0xFFFFFFFFu, ay, 16);
    az += __shfl_xor_sync(0xFFFFFFFFu, az, 16);
    aw += __shfl_xor_sync(0xFFFFFFFFu, aw, 16);

    if (half == 0) {
        size_t idx = (size_t)wg * VEC + il;
        float4 old = __ldg(&src[idx]);
        dst[idx] = make_float4(ax + old.x, ay + old.y, az + old.z, aw + old.w);
    }
}

// one warp per sample; acc row = E0 + E1 + E2 gathered on the fly
__global__ void k_loss(const float* __restrict__ ue, const float* __restrict__ ie,
                       const int* __restrict__ users, const int* __restrict__ pos,
                       const int* __restrict__ neg, float* __restrict__ out) {
    int warp = (blockIdx.x * blockDim.x + threadIdx.x) >> 5;
    int lane = threadIdx.x & 31;
    if (warp >= BATCH) return;
    int u = users[warp], p = pos[warp], n = neg[warp];

    const float2* e0 = reinterpret_cast<const float2*>(g_E0);
    const float2* e1 = reinterpret_cast<const float2*>(g_E1);
    const float2* e2 = reinterpret_cast<const float2*>(g_E2);

    size_t ui = (size_t)u * 32 + lane;
    size_t pi = (size_t)(N_USERS + p) * 32 + lane;
    size_t ni = (size_t)(N_USERS + n) * 32 + lane;

    float2 u0 = __ldg(e0 + ui), u1 = __ldg(e1 + ui), u2 = __ldg(e2 + ui);
    float2 p0 = __ldg(e0 + pi), p1 = __ldg(e1 + pi), p2 = __ldg(e2 + pi);
    float2 n0 = __ldg(e0 + ni), n1 = __ldg(e1 + ni), n2 = __ldg(e2 + ni);

    float2 uv = make_float2(u0.x + u1.x + u2.x, u0.y + u1.y + u2.y);
    float2 pv = make_float2(p0.x + p1.x + p2.x, p0.y + p1.y + p2.y);
    float2 nv = make_float2(n0.x + n1.x + n2.x, n0.y + n1.y + n2.y);
    float s = uv.x * (nv.x - pv.x) + uv.y * (nv.y - pv.y);   // neg - pos partial

    const float2* up = reinterpret_cast<const float2*>(ue + (size_t)u * EMB_DIM);
    const float2* pp = reinterpret_cast<const float2*>(ie + (size_t)p * EMB_DIM);
    const float2* np = reinterpret_cast<const float2*>(ie + (size_t)n * EMB_DIM);
    float2 a = __ldg(up + lane), b = __ldg(pp + lane), c = __ldg(np + lane);
    float r = a.x*a.x + a.y*a.y + b.x*b.x + b.y*b.y + c.x*c.x + c.y*c.y;

    #pragma unroll
    for (int o = 16; o; o >>= 1) {
        s += __shfl_xor_sync(0xFFFFFFFFu, s, o);
        r += __shfl_xor_sync(0xFFFFFFFFu, r, o);
    }
    if (lane == 0) {
        float x  = s;
        float sp = (x > 0.0f) ? x + log1pf(expf(-x)) : log1pf(expf(x));
        atomicAdd(&out[0], sp * (1.0f / BATCH));
        atomicAdd(&out[1], r * EMB_REG);
    }
}

// ---------------- launch ----------------
extern "C" void kernel_launch(void* const* d_in, const int* in_sizes, int n_in,
                              void* d_out, int out_size) {
    const float* ue    = (const float*)d_in[0];
    const float* ie    = (const float*)d_in[1];
    const int*   all_h = (const int*)  d_in[2];
    const int*   all_t = (const int*)  d_in[3];
    const int*   users = (const int*)  d_in[4];
    const int*   pos   = (const int*)  d_in[5];
    const int*   neg   = (const int*)  d_in[6];
    float*       out   = (float*)d_out;

    const int T = 256;
    const int gNode = (N_NODES + T - 1) / T;
    const int gEdge = (N_EDGES + T - 1) / T;
    const int gVec  = (N_NODES * VEC + T - 1) / T;
    const int gMark = (NEEDED + T - 1) / T;
    const int gM1   = ((NEEDED * 32) + T - 1) / T;    // warp per needed row (closure mark)
    const int gCsr1 = ((N_NODES * 32) + T - 1) / T;   // worst-case closure size
    const int gCsr2 = ((NEEDED  * 32) + T - 1) / T;   // warp per needed row

    k_zero        <<<gNode, T>>>(out);
    k_deg         <<<gEdge, T>>>(all_h);
    k_scan1       <<<NBLK, SCAN_BLK>>>();
    k_scan2       <<<1, 1024>>>();
    k_scan3       <<<gNode, T>>>();
    k_scatter_init<<<gEdge + gVec + gMark, T>>>(all_h, all_t, ue, ie,
                                                users, pos, neg, gEdge, gVec);
    k_mark1       <<<gM1, T>>>();

    k_csr1<<<gCsr1, T>>>();
    k_csr2<<<gCsr2, T>>>();

    k_loss<<<(BATCH * 32 + T - 1) / T, T>>>(ue, ie, users, pos, neg, out);
}